// round 3
// baseline (speedup 1.0000x reference)
#include <cuda_runtime.h>
#include <math.h>

// Problem constants (fixed by setup_inputs)
#define BB    2
#define NN    2048
#define FIN   256
#define CC    64              // feature width of both layers (8 heads * 8 = 64, Fout = 64)
#define MM    (BB*NN)         // 4096 rows
#define EMAX  32768
#define ALPHA 0.2f            // leaky_relu slope

// ---------------- scratch (device globals; no allocation allowed) ----------------
static __device__ float g_h1[MM*CC];
static __device__ float g_x1[MM*CC];
static __device__ float g_h2[MM*CC];
static __device__ float g_pre[MM*CC];
static __device__ float g_s1a[8*MM];
static __device__ float g_s2a[8*MM];
static __device__ float g_s1b[MM];
static __device__ float g_s2b[MM];
static __device__ float g_W1[FIN*CC];
static __device__ unsigned g_bitmap[(NN*NN)/32];   // 512 KB dedup bitmap
static __device__ int g_deg[NN];
static __device__ int g_rowstart[NN+1];
static __device__ int g_cursor[NN];
static __device__ int g_adj[EMAX];
static __device__ unsigned char g_valid[EMAX];

// ---------------- K0: clear bitmap/deg + pack W_h [8,256,8] -> W1 [256,64] ----------------
__global__ void k_prep(const float* __restrict__ Wh) {
    int i = blockIdx.x * blockDim.x + threadIdx.x;    // 131072 threads
    if (i < (NN*NN)/32) g_bitmap[i] = 0u;
    if (i < NN) g_deg[i] = 0;
    if (i < 8*FIN*8) {
        int h = i >> 11;            // i / 2048
        int r = i & 2047;
        int f = r >> 3;
        int o = r & 7;
        g_W1[f*CC + h*8 + o] = Wh[i];
    }
}

// ---------------- K1: dedupe edges, count degrees ----------------
__global__ void k_dedup(const int* __restrict__ edges, int E) {
    int e = blockIdx.x * blockDim.x + threadIdx.x;
    if (e >= E) return;
    int s = edges[e];
    int t = edges[E + e];
    unsigned cell = (unsigned)s * NN + (unsigned)t;
    unsigned mask = 1u << (cell & 31u);
    unsigned old = atomicOr(&g_bitmap[cell >> 5], mask);
    if ((old & mask) == 0u) {
        g_valid[e] = 1;
        atomicAdd(&g_deg[s], 1);
    } else {
        g_valid[e] = 0;
    }
}

// ---------------- K2: exclusive scan of degrees -> CSR row starts ----------------
__global__ void k_scan() {
    __shared__ int p[1024];
    int t = threadIdx.x;                 // 1024 threads, 2 deg each
    int d0 = g_deg[2*t];
    int d1 = g_deg[2*t + 1];
    int ps = d0 + d1;
    p[t] = ps;
    __syncthreads();
    for (int off = 1; off < 1024; off <<= 1) {
        int v = (t >= off) ? p[t - off] : 0;
        __syncthreads();
        p[t] += v;
        __syncthreads();
    }
    int base = p[t] - ps;                // exclusive prefix of the pair
    g_rowstart[2*t]     = base;      g_cursor[2*t]     = base;
    g_rowstart[2*t + 1] = base + d0; g_cursor[2*t + 1] = base + d0;
    if (t == 1023) g_rowstart[NN] = p[1023];
}

// ---------------- K3: scatter deduped edges into CSR ----------------
__global__ void k_scatter(const int* __restrict__ edges, int E) {
    int e = blockIdx.x * blockDim.x + threadIdx.x;
    if (e >= E) return;
    if (!g_valid[e]) return;
    int s = edges[e];
    int pos = atomicAdd(&g_cursor[s], 1);
    g_adj[pos] = edges[E + e];
}

// ---------------- GEMM body: C[M x 64] = A[M x K] * W[K x 64]  + fused score epilogue ----
// block = 256 threads computes a 64x64 tile; thread = 4x4 micro tile.
// Epilogue: s1[m] = C[m,:] . a[:O] slices, s2[m] = C[m,:] . a[O:] slices (per head).
template<int HH, int OW>
__device__ __forceinline__ void gemm_body(const float* __restrict__ A,
                                          const float* __restrict__ W,
                                          const float* __restrict__ avec,
                                          float* __restrict__ C,
                                          float* __restrict__ s1,
                                          float* __restrict__ s2, int K) {
    __shared__ float As[64][65];
    __shared__ float Ws[64][64];
    __shared__ float Cs[64][64];      // NO padding: row stride 256B keeps float4 stores aligned
    int tid = threadIdx.x;
    int tx = tid & 15;        // col group
    int ty = tid >> 4;        // row group
    int m0 = blockIdx.x * 64;
    float acc[4][4] = {};
    for (int k0 = 0; k0 < K; k0 += 64) {
        #pragma unroll
        for (int i = tid; i < 4096; i += 256) {
            int r = i >> 6, c = i & 63;
            As[r][c] = A[(m0 + r) * K + k0 + c];
            Ws[r][c] = W[(k0 + r) * 64 + c];
        }
        __syncthreads();
        #pragma unroll 8
        for (int kk = 0; kk < 64; kk++) {
            float a[4];
            #pragma unroll
            for (int i = 0; i < 4; i++) a[i] = As[ty*4 + i][kk];
            float4 b4 = *reinterpret_cast<const float4*>(&Ws[kk][tx*4]);
            float b[4] = {b4.x, b4.y, b4.z, b4.w};
            #pragma unroll
            for (int i = 0; i < 4; i++)
                #pragma unroll
                for (int j = 0; j < 4; j++)
                    acc[i][j] = fmaf(a[i], b[j], acc[i][j]);
        }
        __syncthreads();
    }
    #pragma unroll
    for (int i = 0; i < 4; i++) {
        float4 o4 = make_float4(acc[i][0], acc[i][1], acc[i][2], acc[i][3]);
        *reinterpret_cast<float4*>(&C[(m0 + ty*4 + i) * CC + tx*4]) = o4;
        *reinterpret_cast<float4*>(&Cs[ty*4 + i][tx*4]) = o4;
    }
    __syncthreads();
    // epilogue: 64 rows, 4 threads per row compute HH head-score pairs (scalar LDS)
    int r  = tid >> 2;           // row 0..63
    int q  = tid & 3;            // quarter
    int m  = m0 + r;
    for (int hh = q; hh < HH; hh += 4) {
        float d1 = 0.f, d2 = 0.f;
        #pragma unroll 8
        for (int o = 0; o < OW; o++) {
            float v = Cs[r][hh*OW + o];
            d1 = fmaf(v, avec[hh*2*OW + o],      d1);
            d2 = fmaf(v, avec[hh*2*OW + OW + o], d2);
        }
        s1[hh*MM + m] = d1;
        s2[hh*MM + m] = d2;
    }
}

__global__ void k_gemm1(const float* __restrict__ x, const float* __restrict__ ah) {
    gemm_body<8, 8>(x, g_W1, ah, g_h1, g_s1a, g_s2a, FIN);
}
__global__ void k_gemm2(const float* __restrict__ Wo, const float* __restrict__ ao) {
    gemm_body<1, 64>(g_x1, Wo, ao, g_h2, g_s1b, g_s2b, CC);
}

// ---------------- edge-softmax aggregation: one warp per (b, src) ----------------
// lane owns features f0=2*lane, f0+1; head hh = f0/OW; subgroup of OW/2 lanes per head.
template<int HH, int OW, bool DOELU>
__device__ __forceinline__ void agg_body(const float* __restrict__ h,
                                         const float* __restrict__ s1,
                                         const float* __restrict__ s2,
                                         const float* __restrict__ bias,
                                         float* __restrict__ o) {
    int gw = (blockIdx.x * blockDim.x + threadIdx.x) >> 5;   // global warp = row m
    if (gw >= MM) return;
    int lane = threadIdx.x & 31;
    int b = gw / NN;
    int src = gw - b * NN;
    int f0 = lane * 2;
    const int hh = f0 / OW;           // compile-time OW -> cheap
    const int GS = OW / 2;            // lanes sharing a head: 4 (layer1) / 32 (layer2)
    int start = g_rowstart[src];
    int end   = g_rowstart[src + 1];
    float z0, z1;
    if (end == start) {
        // empty row: softmax over all-NEG row is uniform 1/N -> column mean of h
        float a0 = 0.f, a1 = 0.f;
        const float* hb = h + b * NN * CC;
        for (int n = 0; n < NN; n++) { a0 += hb[n*CC + f0]; a1 += hb[n*CC + f0 + 1]; }
        z0 = a0 * (1.0f / NN);
        z1 = a1 * (1.0f / NN);
    } else {
        float sv = s1[hh*MM + gw];
        const float* s2h = s2 + hh*MM + b*NN;
        // phase A: per-head max over this row's edges (subgroup-parallel)
        float mx = -INFINITY;
        for (int j = start + (lane & (GS - 1)); j < end; j += GS) {
            int t = g_adj[j];
            float e = sv + s2h[t];
            e = e > 0.f ? e : ALPHA * e;
            mx = fmaxf(mx, e);
        }
        #pragma unroll
        for (int off = GS >> 1; off; off >>= 1)
            mx = fmaxf(mx, __shfl_xor_sync(0xffffffffu, mx, off));
        // phase B: serial over edges, coalesced 256B reads of h[tgt]
        float sw = 0.f, a0 = 0.f, a1 = 0.f;
        for (int j = start; j < end; j++) {
            int t = g_adj[j];
            float e = sv + s2h[t];
            e = e > 0.f ? e : ALPHA * e;
            float w = expf(e - mx);
            sw += w;
            const float* hr = h + (b*NN + t) * CC + f0;
            a0 += w * hr[0];
            a1 += w * hr[1];
        }
        float inv = 1.0f / sw;
        z0 = a0 * inv;
        z1 = a1 * inv;
    }
    z0 += bias[f0];
    z1 += bias[f0 + 1];
    if (DOELU) {
        z0 = z0 > 0.f ? z0 : expm1f(z0);
        z1 = z1 > 0.f ? z1 : expm1f(z1);
    }
    o[gw*CC + f0]     = z0;
    o[gw*CC + f0 + 1] = z1;
}

__global__ void k_agg1(const float* __restrict__ bh) { agg_body<8, 8,  true >(g_h1, g_s1a, g_s2a, bh, g_x1);  }
__global__ void k_agg2(const float* __restrict__ bo) { agg_body<1, 64, false>(g_h2, g_s1b, g_s2b, bo, g_pre); }

// ---------------- log_softmax over node axis (per (b, channel)) ----------------
__global__ void k_lsm(float* __restrict__ out) {
    int b = blockIdx.x >> 6;
    int f = blockIdx.x & 63;
    int t = threadIdx.x;   // 256 threads, 8 nodes each
    float v[8];
    float mx = -INFINITY;
    #pragma unroll
    for (int i = 0; i < 8; i++) {
        v[i] = g_pre[(b*NN + i*256 + t) * CC + f];
        mx = fmaxf(mx, v[i]);
    }
    __shared__ float red[256];
    red[t] = mx; __syncthreads();
    for (int s = 128; s; s >>= 1) { if (t < s) red[t] = fmaxf(red[t], red[t + s]); __syncthreads(); }
    mx = red[0];
    __syncthreads();
    float sm = 0.f;
    #pragma unroll
    for (int i = 0; i < 8; i++) sm += expf(v[i] - mx);
    red[t] = sm; __syncthreads();
    for (int s = 128; s; s >>= 1) { if (t < s) red[t] += red[t + s]; __syncthreads(); }
    float l = mx + logf(red[0]);
    #pragma unroll
    for (int i = 0; i < 8; i++) out[(b*NN + i*256 + t) * CC + f] = v[i] - l;
}

// ---------------- launch ----------------
extern "C" void kernel_launch(void* const* d_in, const int* in_sizes, int n_in,
                              void* d_out, int out_size) {
    const float* x     = (const float*)d_in[0];
    const int*   edges = (const int*)  d_in[1];
    const float* Wh    = (const float*)d_in[2];
    const float* ah    = (const float*)d_in[3];
    const float* bh    = (const float*)d_in[4];
    const float* Wo    = (const float*)d_in[5];
    const float* ao    = (const float*)d_in[6];
    const float* bo    = (const float*)d_in[7];
    float* out = (float*)d_out;
    int E = in_sizes[1] / 2;
    if (E > EMAX) E = EMAX;   // defensive clamp; dataset uses E = 32768

    k_prep   <<<512, 256>>>(Wh);
    k_dedup  <<<(E + 255) / 256, 256>>>(edges, E);
    k_scan   <<<1, 1024>>>();
    k_scatter<<<(E + 255) / 256, 256>>>(edges, E);

    k_gemm1  <<<MM / 64, 256>>>(x, ah);
    k_agg1   <<<(MM * 32) / 256, 256>>>(bh);

    k_gemm2  <<<MM / 64, 256>>>(Wo, ao);
    k_agg2   <<<(MM * 32) / 256, 256>>>(bo);

    k_lsm    <<<BB * CC, 256>>>(out);
}

// round 5
// speedup vs baseline: 1.1935x; 1.1935x over previous
#include <cuda_runtime.h>
#include <math.h>

// Problem constants (fixed by setup_inputs)
#define BB    2
#define NN    2048
#define FIN   256
#define CC    64              // feature width of both layers (8 heads * 8 = 64, Fout = 64)
#define MM    (BB*NN)         // 4096 rows
#define EMAX  32768
#define CAP   64              // per-node adjacency bucket capacity (Poisson(16) -> safe)
#define ALPHA 0.2f            // leaky_relu slope

// ---------------- scratch (device globals; no allocation allowed) ----------------
static __device__ __align__(16) float g_h1[MM*CC];
static __device__ __align__(16) float g_x1[MM*CC];
static __device__ __align__(16) float g_h2[MM*CC];
static __device__ __align__(16) float g_pre[MM*CC];
static __device__ float g_s1a[8*MM];
static __device__ float g_s2a[8*MM];
static __device__ float g_s1b[MM];
static __device__ float g_s2b[MM];
static __device__ int g_deg[NN];        // zeros at module load; re-zeroed by k_lsm each call
static __device__ int g_adj[NN*CAP];    // bucketed adjacency (targets), 512 KB

// ---------------- GEMM body: C[M x 64] = A[M x K] * W[K x 64]  + fused score epilogue ----
// block = 256 threads computes a 32x64 tile (128 blocks); thread = 2x4 micro tile.
// LAYER==1: K=256, W loaded from raw W_h [8,256,8] with inline repack to [256,64].
// LAYER==2: K=64,  W is W_o [64,64] directly.
// Epilogue computes s1[m] = C[m,:].a[:O], s2[m] = C[m,:].a[O:] per head.
template<int LAYER>
__device__ __forceinline__ void gemm_body(const float* __restrict__ A,
                                          const float* __restrict__ Wraw,
                                          const float* __restrict__ avec,
                                          float* __restrict__ C,
                                          float* __restrict__ s1,
                                          float* __restrict__ s2) {
    const int K = (LAYER == 1) ? FIN : CC;
    __shared__ float As[32][65];
    __shared__ float Ws[64][64];
    __shared__ float Cs[32][64];     // unpadded: 256B rows keep float4 stores aligned
    int tid = threadIdx.x;
    int tx = tid & 15;        // col group (4 cols)
    int ty = tid >> 4;        // row group (2 rows)
    int m0 = blockIdx.x * 32;
    float acc[2][4] = {};
    for (int k0 = 0; k0 < K; k0 += 64) {
        #pragma unroll
        for (int i = tid; i < 32*64; i += 256) {
            int r = i >> 6, c = i & 63;
            As[r][c] = A[(m0 + r) * K + k0 + c];
        }
        #pragma unroll
        for (int i = tid; i < 64*64; i += 256) {
            int r = i >> 6, c = i & 63;
            Ws[r][c] = (LAYER == 1)
                ? Wraw[(c >> 3) * (FIN*8) + (k0 + r) * 8 + (c & 7)]   // W_h[h][f][o]
                : Wraw[(k0 + r) * 64 + c];
        }
        __syncthreads();
        #pragma unroll 8
        for (int kk = 0; kk < 64; kk++) {
            float a0 = As[ty*2    ][kk];
            float a1 = As[ty*2 + 1][kk];
            float4 b4 = *reinterpret_cast<const float4*>(&Ws[kk][tx*4]);
            float b[4] = {b4.x, b4.y, b4.z, b4.w};
            #pragma unroll
            for (int j = 0; j < 4; j++) {
                acc[0][j] = fmaf(a0, b[j], acc[0][j]);
                acc[1][j] = fmaf(a1, b[j], acc[1][j]);
            }
        }
        __syncthreads();
    }
    #pragma unroll
    for (int i = 0; i < 2; i++) {
        float4 o4 = make_float4(acc[i][0], acc[i][1], acc[i][2], acc[i][3]);
        *reinterpret_cast<float4*>(&C[(m0 + ty*2 + i) * CC + tx*4]) = o4;
        *reinterpret_cast<float4*>(&Cs[ty*2 + i][tx*4]) = o4;
    }
    __syncthreads();
    // score epilogue: 8 threads per row
    int r = tid >> 3;        // row 0..31
    int q = tid & 7;         // 0..7
    int m = m0 + r;
    if (LAYER == 1) {
        // 8 heads of width 8: thread q owns head q entirely
        float d1 = 0.f, d2 = 0.f;
        #pragma unroll
        for (int o = 0; o < 8; o++) {
            float v = Cs[r][q*8 + o];
            d1 = fmaf(v, avec[q*16 + o],     d1);
            d2 = fmaf(v, avec[q*16 + 8 + o], d2);
        }
        s1[q*MM + m] = d1;
        s2[q*MM + m] = d2;
    } else {
        // 1 head of width 64: 8 threads split the dot, shfl-reduce in 8-lane groups
        float d1 = 0.f, d2 = 0.f;
        #pragma unroll
        for (int o = 0; o < 8; o++) {
            float v = Cs[r][q*8 + o];
            d1 = fmaf(v, avec[q*8 + o],      d1);
            d2 = fmaf(v, avec[64 + q*8 + o], d2);
        }
        #pragma unroll
        for (int off = 4; off; off >>= 1) {
            d1 += __shfl_down_sync(0xffffffffu, d1, off, 8);
            d2 += __shfl_down_sync(0xffffffffu, d2, off, 8);
        }
        if (q == 0) { s1[m] = d1; s2[m] = d2; }
    }
}

// gemm1 also builds the bucketed adjacency as a prologue (results consumed by agg1,
// which launches strictly after this kernel completes).
__global__ void k_gemm1(const float* __restrict__ x, const float* __restrict__ Wh,
                        const float* __restrict__ ah,
                        const int* __restrict__ edges, int E) {
    int e = blockIdx.x * blockDim.x + threadIdx.x;    // 128*256 = 32768 >= E
    if (e < E) {
        int s = edges[e];
        int t = edges[E + e];
        int pos = atomicAdd(&g_deg[s], 1);
        if (pos < CAP) g_adj[s*CAP + pos] = t;
    }
    gemm_body<1>(x, Wh, ah, g_h1, g_s1a, g_s2a);
}
__global__ void k_gemm2(const float* __restrict__ Wo, const float* __restrict__ ao) {
    gemm_body<2>(g_x1, Wo, ao, g_h2, g_s1b, g_s2b);
}

// ---------------- edge-softmax aggregation: one warp per (b, src) row ----------------
// lane owns features f0=2*lane, f0+1; head hh = f0/OW; GS = OW/2 lanes share a head.
// Dedup: duplicate (src,tgt) pairs must count ONCE (reference uses .set on a dense cell).
// Duplicates have identical e, so they are harmless for the max; for the sum they get w=0.
template<int OW, bool DOELU>
__device__ __forceinline__ void agg_body(const float* __restrict__ h,
                                         const float* __restrict__ s1,
                                         const float* __restrict__ s2,
                                         const float* __restrict__ bias,
                                         float* __restrict__ o) {
    int warp = threadIdx.x >> 5;
    int gw   = blockIdx.x * 8 + warp;      // row m in [0, MM)
    int lane = threadIdx.x & 31;
    __shared__ int ts_all[8][CAP];
    int* ts = ts_all[warp];
    int b   = gw >> 11;                    // / NN
    int src = gw & (NN - 1);
    int f0  = lane * 2;
    const int hh = (OW == 8) ? (lane >> 2) : 0;
    const int GS = OW / 2;                 // 4 (layer1) / 32 (layer2)
    int d = g_deg[src]; if (d > CAP) d = CAP;
    float z0, z1;
    if (d == 0) {
        // empty row: softmax over all-NEG row is uniform 1/N -> column mean of h
        float a0 = 0.f, a1 = 0.f;
        const float* hb = h + b * NN * CC;
        for (int n = 0; n < NN; n++) { a0 += hb[n*CC + f0]; a1 += hb[n*CC + f0 + 1]; }
        z0 = a0 * (1.0f / NN);
        z1 = a1 * (1.0f / NN);
    } else {
        // stage targets in smem
        for (int j = lane; j < d; j += 32) ts[j] = g_adj[src*CAP + j];
        __syncwarp();
        // duplicate flags (reads only; writes deferred past phase A)
        int  t0 = -1, t1 = -1;
        bool dup0 = false, dup1 = false;
        if (lane < d)      { t0 = ts[lane];      for (int i = 0; i < lane;      i++) dup0 |= (ts[i] == t0); }
        if (lane + 32 < d) { t1 = ts[lane + 32]; for (int i = 0; i < lane + 32; i++) dup1 |= (ts[i] == t1); }
        // phase A: per-head max (dups included harmlessly)
        float sv = s1[hh*MM + gw];
        const float* s2h = s2 + hh*MM + b*NN;
        float mx = -INFINITY;
        for (int j = (lane & (GS - 1)); j < d; j += GS) {
            float e = sv + s2h[ts[j]];
            e = e > 0.f ? e : ALPHA * e;
            mx = fmaxf(mx, e);
        }
        #pragma unroll
        for (int off = GS >> 1; off; off >>= 1)
            mx = fmaxf(mx, __shfl_xor_sync(0xffffffffu, mx, off));
        __syncwarp();
        if (lane < d && dup0)      ts[lane]      = -1;
        if (lane + 32 < d && dup1) ts[lane + 32] = -1;
        __syncwarp();
        // phase B: serial over edges; branchless dup-skip; unrolled for MLP
        float sw = 0.f, a0 = 0.f, a1 = 0.f;
        const float* hb = h + b * NN * CC + f0;
        #pragma unroll 2
        for (int j = 0; j < d; j++) {
            int t = ts[j];
            float valid = (t >= 0) ? 1.f : 0.f;
            int tt = (t >= 0) ? t : 0;
            float e = sv + s2h[tt];
            e = e > 0.f ? e : ALPHA * e;
            float w = valid * expf(e - mx);
            sw += w;
            const float* hr = hb + tt * CC;
            a0 = fmaf(w, hr[0], a0);
            a1 = fmaf(w, hr[1], a1);
        }
        float inv = 1.0f / sw;
        z0 = a0 * inv;
        z1 = a1 * inv;
    }
    z0 += bias[f0];
    z1 += bias[f0 + 1];
    if (DOELU) {
        z0 = z0 > 0.f ? z0 : expm1f(z0);
        z1 = z1 > 0.f ? z1 : expm1f(z1);
    }
    o[gw*CC + f0]     = z0;
    o[gw*CC + f0 + 1] = z1;
}

__global__ void k_agg1(const float* __restrict__ bh) { agg_body<8,  true >(g_h1, g_s1a, g_s2a, bh, g_x1);  }
__global__ void k_agg2(const float* __restrict__ bo) { agg_body<64, false>(g_h2, g_s1b, g_s2b, bo, g_pre); }

// ---------------- log_softmax over node axis (per (b, channel)) + deg re-zero ----------------
__global__ void k_lsm(float* __restrict__ out) {
    // re-establish g_deg == 0 for the next kernel_launch call (module load provides
    // the initial zeros; every call ends by restoring the invariant).
    int gt = blockIdx.x * blockDim.x + threadIdx.x;
    if (gt < NN) g_deg[gt] = 0;

    int b = blockIdx.x >> 6;
    int f = blockIdx.x & 63;
    int t = threadIdx.x;   // 256 threads, 8 nodes each
    float v[8];
    float mx = -INFINITY;
    #pragma unroll
    for (int i = 0; i < 8; i++) {
        v[i] = g_pre[(b*NN + i*256 + t) * CC + f];
        mx = fmaxf(mx, v[i]);
    }
    __shared__ float red[256];
    red[t] = mx; __syncthreads();
    for (int s = 128; s; s >>= 1) { if (t < s) red[t] = fmaxf(red[t], red[t + s]); __syncthreads(); }
    mx = red[0];
    __syncthreads();
    float sm = 0.f;
    #pragma unroll
    for (int i = 0; i < 8; i++) sm += expf(v[i] - mx);
    red[t] = sm; __syncthreads();
    for (int s = 128; s; s >>= 1) { if (t < s) red[t] += red[t + s]; __syncthreads(); }
    float l = mx + logf(red[0]);
    #pragma unroll
    for (int i = 0; i < 8; i++) out[(b*NN + i*256 + t) * CC + f] = v[i] - l;
}

// ---------------- launch: 5 kernels ----------------
extern "C" void kernel_launch(void* const* d_in, const int* in_sizes, int n_in,
                              void* d_out, int out_size) {
    const float* x     = (const float*)d_in[0];
    const int*   edges = (const int*)  d_in[1];
    const float* Wh    = (const float*)d_in[2];
    const float* ah    = (const float*)d_in[3];
    const float* bh    = (const float*)d_in[4];
    const float* Wo    = (const float*)d_in[5];
    const float* ao    = (const float*)d_in[6];
    const float* bo    = (const float*)d_in[7];
    float* out = (float*)d_out;
    int E = in_sizes[1] / 2;
    if (E > EMAX) E = EMAX;   // defensive clamp; dataset uses E = 32768

    k_gemm1<<<MM/32, 256>>>(x, Wh, ah, edges, E);   // + adjacency build prologue
    k_agg1 <<<MM/8,  256>>>(bh);
    k_gemm2<<<MM/32, 256>>>(Wo, ao);
    k_agg2 <<<MM/8,  256>>>(bo);
    k_lsm  <<<BB*CC, 256>>>(out);                   // + deg re-zero epilogue
}

// round 6
// speedup vs baseline: 1.3474x; 1.1289x over previous
#include <cuda_runtime.h>
#include <math.h>

// Problem constants (fixed by setup_inputs)
#define BB    2
#define NN    2048
#define FIN   256
#define CC    64              // feature width of both layers (8 heads * 8 = 64, Fout = 64)
#define MM    (BB*NN)         // 4096 rows
#define EMAX  32768
#define CAP   64              // per-node adjacency bucket capacity (Poisson(16) -> safe)
#define ALPHA 0.2f            // leaky_relu slope

// ---------------- scratch (device globals; no allocation allowed) ----------------
static __device__ __align__(16) float g_h1[MM*CC];
static __device__ __align__(16) float g_x1[MM*CC];
static __device__ __align__(16) float g_h2[MM*CC];
static __device__ __align__(16) float g_pre[MM*CC];
static __device__ float g_s1a[8*MM];
static __device__ float g_s2a[8*MM];
static __device__ float g_s1b[MM];
static __device__ float g_s2b[MM];
static __device__ int g_deg[NN];        // zeros at module load; re-zeroed by k_lsm each call
static __device__ int g_adj[NN*CAP];    // bucketed adjacency (targets), 512 KB

// ---------------- GEMM body: C[M x 64] = A[M x K] * W[K x 64]  + fused score epilogue ----
// block = 256 threads computes a 32x64 tile (128 blocks); thread = 2x4 micro tile.
// LAYER==1: K=256, W loaded from raw W_h [8,256,8] with inline repack to [256,64].
// LAYER==2: K=64,  W is W_o [64,64] directly.
template<int LAYER>
__device__ __forceinline__ void gemm_body(const float* __restrict__ A,
                                          const float* __restrict__ Wraw,
                                          const float* __restrict__ avec,
                                          float* __restrict__ C,
                                          float* __restrict__ s1,
                                          float* __restrict__ s2) {
    const int K = (LAYER == 1) ? FIN : CC;
    __shared__ float As[32][65];
    __shared__ float Ws[64][64];
    __shared__ float Cs[32][64];     // unpadded: 256B rows keep float4 stores aligned
    int tid = threadIdx.x;
    int tx = tid & 15;        // col group (4 cols)
    int ty = tid >> 4;        // row group (2 rows)
    int m0 = blockIdx.x * 32;
    float acc[2][4] = {};
    for (int k0 = 0; k0 < K; k0 += 64) {
        #pragma unroll
        for (int i = tid; i < 32*64; i += 256) {
            int r = i >> 6, c = i & 63;
            As[r][c] = A[(m0 + r) * K + k0 + c];
        }
        #pragma unroll
        for (int i = tid; i < 64*64; i += 256) {
            int r = i >> 6, c = i & 63;
            Ws[r][c] = (LAYER == 1)
                ? Wraw[(c >> 3) * (FIN*8) + (k0 + r) * 8 + (c & 7)]   // W_h[h][f][o]
                : Wraw[(k0 + r) * 64 + c];
        }
        __syncthreads();
        #pragma unroll 8
        for (int kk = 0; kk < 64; kk++) {
            float a0 = As[ty*2    ][kk];
            float a1 = As[ty*2 + 1][kk];
            float4 b4 = *reinterpret_cast<const float4*>(&Ws[kk][tx*4]);
            float b[4] = {b4.x, b4.y, b4.z, b4.w};
            #pragma unroll
            for (int j = 0; j < 4; j++) {
                acc[0][j] = fmaf(a0, b[j], acc[0][j]);
                acc[1][j] = fmaf(a1, b[j], acc[1][j]);
            }
        }
        __syncthreads();
    }
    #pragma unroll
    for (int i = 0; i < 2; i++) {
        float4 o4 = make_float4(acc[i][0], acc[i][1], acc[i][2], acc[i][3]);
        *reinterpret_cast<float4*>(&C[(m0 + ty*2 + i) * CC + tx*4]) = o4;
        *reinterpret_cast<float4*>(&Cs[ty*2 + i][tx*4]) = o4;
    }
    __syncthreads();
    // score epilogue: 8 threads per row
    int r = tid >> 3;        // row 0..31
    int q = tid & 7;         // 0..7
    int m = m0 + r;
    if (LAYER == 1) {
        // 8 heads of width 8: thread q owns head q entirely
        float d1 = 0.f, d2 = 0.f;
        #pragma unroll
        for (int o = 0; o < 8; o++) {
            float v = Cs[r][q*8 + o];
            d1 = fmaf(v, avec[q*16 + o],     d1);
            d2 = fmaf(v, avec[q*16 + 8 + o], d2);
        }
        s1[q*MM + m] = d1;
        s2[q*MM + m] = d2;
    } else {
        // 1 head of width 64: 8 threads split the dot, shfl-reduce in 8-lane groups
        float d1 = 0.f, d2 = 0.f;
        #pragma unroll
        for (int o = 0; o < 8; o++) {
            float v = Cs[r][q*8 + o];
            d1 = fmaf(v, avec[q*8 + o],      d1);
            d2 = fmaf(v, avec[64 + q*8 + o], d2);
        }
        #pragma unroll
        for (int off = 4; off; off >>= 1) {
            d1 += __shfl_down_sync(0xffffffffu, d1, off, 8);
            d2 += __shfl_down_sync(0xffffffffu, d2, off, 8);
        }
        if (q == 0) { s1[m] = d1; s2[m] = d2; }
    }
}

// gemm1 also builds the bucketed adjacency as a prologue (results consumed by agg1,
// which launches strictly after this kernel completes).
__global__ void k_gemm1(const float* __restrict__ x, const float* __restrict__ Wh,
                        const float* __restrict__ ah,
                        const int* __restrict__ edges, int E) {
    int e = blockIdx.x * blockDim.x + threadIdx.x;    // 128*256 = 32768 >= E
    if (e < E) {
        int s = edges[e];
        int t = edges[E + e];
        int pos = atomicAdd(&g_deg[s], 1);
        if (pos < CAP) g_adj[s*CAP + pos] = t;
    }
    gemm_body<1>(x, Wh, ah, g_h1, g_s1a, g_s2a);
}
__global__ void k_gemm2(const float* __restrict__ Wo, const float* __restrict__ ao) {
    gemm_body<2>(g_x1, Wo, ao, g_h2, g_s1b, g_s2b);
}

// ---------------- edge-softmax aggregation: one warp per (b, src) row ----------------
// lane owns features f0=2*lane, f0+1; head hh = f0/OW; GS = OW/2 lanes share a head.
// Weights are computed in PARALLEL across each head's lane subgroup and staged in smem;
// the serial phase B is then just (LDS w, LDS t, LDG.64 h, 2xFMA) per edge.
// Dedup: duplicate (src,tgt) pairs must count ONCE (reference uses dense-cell .set);
// duplicates get ts[j] = -1 -> w = 0 and are excluded from the max.
template<int HH, int OW, bool DOELU>
__device__ __forceinline__ void agg_body(const float* __restrict__ h,
                                         const float* __restrict__ s1,
                                         const float* __restrict__ s2,
                                         const float* __restrict__ bias,
                                         float* __restrict__ o) {
    const int GS = OW / 2;                 // 4 (layer1) / 32 (layer2)
    __shared__ int   ts_all[8][CAP];
    __shared__ float w_all[8][HH*(CAP+1)]; // +1 pad: head index -> distinct banks
    int warp = threadIdx.x >> 5;
    int gw   = blockIdx.x * 8 + warp;      // row m in [0, MM)
    int lane = threadIdx.x & 31;
    int* ts  = ts_all[warp];
    int b    = gw >> 11;                   // / NN
    int src  = gw & (NN - 1);
    int f0   = lane * 2;
    const int hh = (OW == 8) ? (lane >> 2) : 0;
    float* wb = w_all[warp] + hh * (CAP+1);
    int d = g_deg[src]; if (d > CAP) d = CAP;
    float z0, z1;
    if (d == 0) {
        // empty row: softmax over all-NEG row is uniform 1/N -> column mean of h
        float a0 = 0.f, a1 = 0.f;
        const float* hb = h + b * NN * CC + f0;
        for (int n = 0; n < NN; n++) {
            float2 hr = *reinterpret_cast<const float2*>(hb + n*CC);
            a0 += hr.x; a1 += hr.y;
        }
        z0 = a0 * (1.0f / NN);
        z1 = a1 * (1.0f / NN);
    } else {
        // stage targets in smem
        for (int j = lane; j < d; j += 32) ts[j] = g_adj[src*CAP + j];
        __syncwarp();
        // duplicate detection (reads), then deferred marking
        int  t0 = -1, t1 = -1;
        bool dup0 = false, dup1 = false;
        if (lane < d)      { t0 = ts[lane];      for (int i = 0; i < lane;      i++) dup0 |= (ts[i] == t0); }
        if (lane + 32 < d) { t1 = ts[lane + 32]; for (int i = 0; i < lane + 32; i++) dup1 |= (ts[i] == t1); }
        __syncwarp();
        if (dup0) ts[lane]      = -1;
        if (dup1) ts[lane + 32] = -1;
        __syncwarp();
        float sv = s1[hh*MM + gw];
        const float* s2h = s2 + hh*MM + b*NN;
        // pass 1 (parallel over subgroup): e_j -> smem, subgroup max (dups excluded)
        float mx = -INFINITY;
        for (int j = (lane & (GS - 1)); j < d; j += GS) {
            int t = ts[j];
            int tt = t < 0 ? 0 : t;
            float e = sv + s2h[tt];
            e = e > 0.f ? e : ALPHA * e;
            wb[j] = e;
            if (t >= 0) mx = fmaxf(mx, e);
        }
        #pragma unroll
        for (int off = GS >> 1; off; off >>= 1)
            mx = fmaxf(mx, __shfl_xor_sync(0xffffffffu, mx, off));
        // pass 2 (parallel): w_j = exp(e_j - mx) (0 for dups), subgroup sum
        float sw = 0.f;
        for (int j = (lane & (GS - 1)); j < d; j += GS) {
            float w = (ts[j] >= 0) ? __expf(wb[j] - mx) : 0.f;
            wb[j] = w;
            sw += w;
        }
        #pragma unroll
        for (int off = GS >> 1; off; off >>= 1)
            sw += __shfl_xor_sync(0xffffffffu, sw, off);
        __syncwarp();
        // phase B: serial weighted gather, minimal per-edge work
        float a0 = 0.f, a1 = 0.f;
        const float* hb = h + b * NN * CC + f0;
        #pragma unroll 4
        for (int j = 0; j < d; j++) {
            int t = ts[j];
            int tt = t < 0 ? 0 : t;
            float w = wb[j];
            float2 hr = *reinterpret_cast<const float2*>(hb + tt*CC);
            a0 = fmaf(w, hr.x, a0);
            a1 = fmaf(w, hr.y, a1);
        }
        float inv = 1.0f / sw;
        z0 = a0 * inv;
        z1 = a1 * inv;
    }
    z0 += bias[f0];
    z1 += bias[f0 + 1];
    if (DOELU) {
        z0 = z0 > 0.f ? z0 : expm1f(z0);
        z1 = z1 > 0.f ? z1 : expm1f(z1);
    }
    o[gw*CC + f0]     = z0;
    o[gw*CC + f0 + 1] = z1;
}

__global__ void k_agg1(const float* __restrict__ bh) { agg_body<8, 8,  true >(g_h1, g_s1a, g_s2a, bh, g_x1);  }
__global__ void k_agg2(const float* __restrict__ bo) { agg_body<1, 64, false>(g_h2, g_s1b, g_s2b, bo, g_pre); }

// ---------------- log_softmax over node axis + deg re-zero ----------------
// grid = BB*16 blocks; block handles batch b, 4 consecutive features via float4.
__global__ void k_lsm(float* __restrict__ out) {
    // re-establish g_deg == 0 for the next kernel_launch call
    int gt = blockIdx.x * blockDim.x + threadIdx.x;
    if (gt < NN) g_deg[gt] = 0;

    int b  = blockIdx.x >> 4;
    int f0 = (blockIdx.x & 15) * 4;
    int t  = threadIdx.x;   // 256 threads, 8 rows each
    float4 v[8];
    float4 mx = make_float4(-INFINITY, -INFINITY, -INFINITY, -INFINITY);
    #pragma unroll
    for (int i = 0; i < 8; i++) {
        v[i] = *reinterpret_cast<const float4*>(&g_pre[(b*NN + i*256 + t) * CC + f0]);
        mx.x = fmaxf(mx.x, v[i].x); mx.y = fmaxf(mx.y, v[i].y);
        mx.z = fmaxf(mx.z, v[i].z); mx.w = fmaxf(mx.w, v[i].w);
    }
    __shared__ float4 red[256];
    red[t] = mx; __syncthreads();
    for (int s = 128; s; s >>= 1) {
        if (t < s) {
            float4 a = red[t], c = red[t + s];
            red[t] = make_float4(fmaxf(a.x,c.x), fmaxf(a.y,c.y), fmaxf(a.z,c.z), fmaxf(a.w,c.w));
        }
        __syncthreads();
    }
    mx = red[0];
    __syncthreads();
    float4 sm = make_float4(0.f, 0.f, 0.f, 0.f);
    #pragma unroll
    for (int i = 0; i < 8; i++) {
        sm.x += __expf(v[i].x - mx.x); sm.y += __expf(v[i].y - mx.y);
        sm.z += __expf(v[i].z - mx.z); sm.w += __expf(v[i].w - mx.w);
    }
    red[t] = sm; __syncthreads();
    for (int s = 128; s; s >>= 1) {
        if (t < s) {
            float4 a = red[t], c = red[t + s];
            red[t] = make_float4(a.x+c.x, a.y+c.y, a.z+c.z, a.w+c.w);
        }
        __syncthreads();
    }
    sm = red[0];
    float4 l = make_float4(mx.x + logf(sm.x), mx.y + logf(sm.y),
                           mx.z + logf(sm.z), mx.w + logf(sm.w));
    #pragma unroll
    for (int i = 0; i < 8; i++) {
        float4 r = make_float4(v[i].x - l.x, v[i].y - l.y, v[i].z - l.z, v[i].w - l.w);
        *reinterpret_cast<float4*>(&out[(b*NN + i*256 + t) * CC + f0]) = r;
    }
}

// ---------------- launch: 5 kernels ----------------
extern "C" void kernel_launch(void* const* d_in, const int* in_sizes, int n_in,
                              void* d_out, int out_size) {
    const float* x     = (const float*)d_in[0];
    const int*   edges = (const int*)  d_in[1];
    const float* Wh    = (const float*)d_in[2];
    const float* ah    = (const float*)d_in[3];
    const float* bh    = (const float*)d_in[4];
    const float* Wo    = (const float*)d_in[5];
    const float* ao    = (const float*)d_in[6];
    const float* bo    = (const float*)d_in[7];
    float* out = (float*)d_out;
    int E = in_sizes[1] / 2;
    if (E > EMAX) E = EMAX;   // defensive clamp; dataset uses E = 32768

    k_gemm1<<<MM/32, 256>>>(x, Wh, ah, edges, E);   // + adjacency build prologue
    k_agg1 <<<MM/8,  256>>>(bh);
    k_gemm2<<<MM/32, 256>>>(Wo, ao);
    k_agg2 <<<MM/8,  256>>>(bo);
    k_lsm  <<<BB*16, 256>>>(out);                   // + deg re-zero epilogue
}

// round 7
// speedup vs baseline: 1.5336x; 1.1382x over previous
#include <cuda_runtime.h>
#include <math.h>

// Problem constants (fixed by setup_inputs)
#define BB    2
#define NN    2048
#define FIN   256
#define CC    64              // feature width of both layers (8 heads * 8 = 64, Fout = 64)
#define MM    (BB*NN)         // 4096 rows
#define EMAX  32768
#define CAP   64              // per-node adjacency bucket capacity (Poisson(16) -> safe)
#define WBS   (CAP+4)         // weight-buffer stride: bank = 4*l8+g, conflict-free
#define ALPHA 0.2f            // leaky_relu slope

// ---------------- scratch (device globals; no allocation allowed) ----------------
static __device__ __align__(16) float g_h1[MM*CC];
static __device__ __align__(16) float g_x1[MM*CC];
static __device__ __align__(16) float g_h2[MM*CC];
static __device__ __align__(16) float g_pre[MM*CC];
static __device__ float g_s1a[8*MM];
static __device__ float g_s2a[8*MM];
static __device__ float g_s1b[MM];
static __device__ float g_s2b[MM];
static __device__ int g_deg[NN];        // zeros at module load; re-zeroed by k_lsm each call
static __device__ int g_adj[NN*CAP];    // bucketed adjacency (targets), 512 KB

// ---------------- GEMM body: C[M x 64] = A[M x K] * W[K x 64]  + fused score epilogue ----
// block = 256 threads computes a 32x64 tile (128 blocks); thread = 2x4 micro tile.
// LAYER==1: K=256, W loaded from raw W_h [8,256,8] with inline repack to [256,64].
// LAYER==2: K=64,  W is W_o [64,64] directly. All staging via float4.
template<int LAYER>
__device__ __forceinline__ void gemm_body(const float* __restrict__ A,
                                          const float* __restrict__ Wraw,
                                          const float* __restrict__ avec,
                                          float* __restrict__ C,
                                          float* __restrict__ s1,
                                          float* __restrict__ s2) {
    const int K = (LAYER == 1) ? FIN : CC;
    __shared__ float As[32][64];     // unpadded: compute reads are 2-address broadcasts
    __shared__ float Ws[64][64];
    __shared__ float Cs[32][64];
    int tid = threadIdx.x;
    int tx = tid & 15;        // col group (4 cols)
    int ty = tid >> 4;        // row group (2 rows)
    int m0 = blockIdx.x * 32;
    float acc[2][4] = {};
    for (int k0 = 0; k0 < K; k0 += 64) {
        // stage A tile: 512 float4, 2 per thread
        #pragma unroll
        for (int v = 0; v < 2; v++) {
            int idx = tid + v*256;            // 0..511
            int r = idx >> 4, c4 = idx & 15;
            *reinterpret_cast<float4*>(&As[r][c4*4]) =
                *reinterpret_cast<const float4*>(&A[(m0 + r) * K + k0 + c4*4]);
        }
        // stage W tile: 1024 float4, 4 per thread
        #pragma unroll
        for (int v = 0; v < 4; v++) {
            int idx = tid + v*256;            // 0..1023
            int r = idx >> 4, c4 = idx & 15;
            float4 w4;
            if (LAYER == 1) {
                int hh = c4 >> 1, o4 = (c4 & 1) * 4;   // W_h[h][f][o], 16B-aligned groups
                w4 = *reinterpret_cast<const float4*>(&Wraw[hh*(FIN*8) + (k0 + r)*8 + o4]);
            } else {
                w4 = *reinterpret_cast<const float4*>(&Wraw[(k0 + r)*64 + c4*4]);
            }
            *reinterpret_cast<float4*>(&Ws[r][c4*4]) = w4;
        }
        __syncthreads();
        #pragma unroll 8
        for (int kk = 0; kk < 64; kk++) {
            float a0 = As[ty*2    ][kk];
            float a1 = As[ty*2 + 1][kk];
            float4 b4 = *reinterpret_cast<const float4*>(&Ws[kk][tx*4]);
            float b[4] = {b4.x, b4.y, b4.z, b4.w};
            #pragma unroll
            for (int j = 0; j < 4; j++) {
                acc[0][j] = fmaf(a0, b[j], acc[0][j]);
                acc[1][j] = fmaf(a1, b[j], acc[1][j]);
            }
        }
        __syncthreads();
    }
    #pragma unroll
    for (int i = 0; i < 2; i++) {
        float4 o4 = make_float4(acc[i][0], acc[i][1], acc[i][2], acc[i][3]);
        *reinterpret_cast<float4*>(&C[(m0 + ty*2 + i) * CC + tx*4]) = o4;
        *reinterpret_cast<float4*>(&Cs[ty*2 + i][tx*4]) = o4;
    }
    __syncthreads();
    // score epilogue: 8 threads per row
    int r = tid >> 3;        // row 0..31
    int q = tid & 7;         // 0..7
    int m = m0 + r;
    if (LAYER == 1) {
        float d1 = 0.f, d2 = 0.f;
        #pragma unroll
        for (int o = 0; o < 8; o++) {
            float v = Cs[r][q*8 + o];
            d1 = fmaf(v, avec[q*16 + o],     d1);
            d2 = fmaf(v, avec[q*16 + 8 + o], d2);
        }
        s1[q*MM + m] = d1;
        s2[q*MM + m] = d2;
    } else {
        float d1 = 0.f, d2 = 0.f;
        #pragma unroll
        for (int o = 0; o < 8; o++) {
            float v = Cs[r][q*8 + o];
            d1 = fmaf(v, avec[q*8 + o],      d1);
            d2 = fmaf(v, avec[64 + q*8 + o], d2);
        }
        #pragma unroll
        for (int off = 4; off; off >>= 1) {
            d1 += __shfl_down_sync(0xffffffffu, d1, off, 8);
            d2 += __shfl_down_sync(0xffffffffu, d2, off, 8);
        }
        if (q == 0) { s1[m] = d1; s2[m] = d2; }
    }
}

// gemm1 also builds the bucketed adjacency as a prologue
__global__ void k_gemm1(const float* __restrict__ x, const float* __restrict__ Wh,
                        const float* __restrict__ ah,
                        const int* __restrict__ edges, int E) {
    int e = blockIdx.x * blockDim.x + threadIdx.x;    // 128*256 = 32768 >= E
    if (e < E) {
        int s = edges[e];
        int t = edges[E + e];
        int pos = atomicAdd(&g_deg[s], 1);
        if (pos < CAP) g_adj[s*CAP + pos] = t;
    }
    gemm_body<1>(x, Wh, ah, g_h1, g_s1a, g_s2a);
}
__global__ void k_gemm2(const float* __restrict__ Wo, const float* __restrict__ ao) {
    gemm_body<2>(g_x1, Wo, ao, g_h2, g_s1b, g_s2b);
}

// ---------------- edge-softmax aggregation: one warp per (b, src) row ----------------
// Score passes: subgroup of GS = OW/2 lanes per head computes e/w in parallel -> smem.
// Gather: warp = 4 groups x 8 lanes; group g handles edges j = g, g+4, ...; lane l8
// owns features l8*8..l8*8+7 (2 x float4, each group reads a full 256B h row).
// Cross-group reduce: shfl_xor offsets 8, 16. For layer 1, head index == l8.
// Dedup: duplicate (src,tgt) must count once (reference dense-cell .set) -> ts=-1, w=0.
template<int HH, int OW, bool DOELU>
__device__ __forceinline__ void agg_body(const float* __restrict__ h,
                                         const float* __restrict__ s1,
                                         const float* __restrict__ s2,
                                         const float* __restrict__ bias,
                                         float* __restrict__ o) {
    const int GS = OW / 2;                 // 4 (layer1) / 32 (layer2)
    __shared__ int   ts_all[8][CAP];
    __shared__ float w_all[8][HH*WBS];
    int warp = threadIdx.x >> 5;
    int gw   = blockIdx.x * 8 + warp;      // row m in [0, MM)
    int lane = threadIdx.x & 31;
    int* ts  = ts_all[warp];
    float* wbase = w_all[warp];
    int b    = gw >> 11;                   // / NN
    int src  = gw & (NN - 1);
    int g    = lane >> 3;                  // gather group 0..3
    int l8   = lane & 7;                   // lane-in-group; features l8*8..+7; head (layer1)
    const int hh_s = (OW == 8) ? (lane >> 2) : 0;   // head for score passes
    int d = g_deg[src]; if (d > CAP) d = CAP;
    float acc[8] = {};
    float sw = 0.f;
    if (d == 0) {
        // empty row -> uniform 1/N softmax -> column mean of h (essentially dead path)
        const float* hb = h + b * NN * CC + l8 * 8;
        for (int n = g; n < NN; n += 4) {
            float4 p = *reinterpret_cast<const float4*>(hb + n*CC);
            float4 q = *reinterpret_cast<const float4*>(hb + n*CC + 4);
            acc[0]+=p.x; acc[1]+=p.y; acc[2]+=p.z; acc[3]+=p.w;
            acc[4]+=q.x; acc[5]+=q.y; acc[6]+=q.z; acc[7]+=q.w;
        }
    } else {
        // stage targets
        for (int j = lane; j < d; j += 32) ts[j] = g_adj[src*CAP + j];
        __syncwarp();
        // dup detect (reads) then deferred marking
        int  t0 = -1, t1 = -1;
        bool dup0 = false, dup1 = false;
        if (lane < d)      { t0 = ts[lane];      for (int i = 0; i < lane;      i++) dup0 |= (ts[i] == t0); }
        if (lane + 32 < d) { t1 = ts[lane + 32]; for (int i = 0; i < lane + 32; i++) dup1 |= (ts[i] == t1); }
        __syncwarp();
        if (dup0) ts[lane]      = -1;
        if (dup1) ts[lane + 32] = -1;
        __syncwarp();
        float sv = s1[hh_s*MM + gw];
        const float* s2h = s2 + hh_s*MM + b*NN;
        float* wb = wbase + hh_s * WBS;
        // pass 1: e_j -> smem, subgroup max (dups excluded)
        float mx = -INFINITY;
        for (int j = (lane & (GS - 1)); j < d; j += GS) {
            int t = ts[j];
            int tt = t < 0 ? 0 : t;
            float e = sv + s2h[tt];
            e = e > 0.f ? e : ALPHA * e;
            wb[j] = e;
            if (t >= 0) mx = fmaxf(mx, e);
        }
        #pragma unroll
        for (int off = GS >> 1; off; off >>= 1)
            mx = fmaxf(mx, __shfl_xor_sync(0xffffffffu, mx, off));
        // pass 2: w_j = exp(e_j - mx), subgroup sum
        for (int j = (lane & (GS - 1)); j < d; j += GS) {
            float w = (ts[j] >= 0) ? __expf(wb[j] - mx) : 0.f;
            wb[j] = w;
            sw += w;
        }
        #pragma unroll
        for (int off = GS >> 1; off; off >>= 1)
            sw += __shfl_xor_sync(0xffffffffu, sw, off);
        __syncwarp();
        // gather: group g, edges j = g, g+4, ...
        const float* hb = h + b * NN * CC + l8 * 8;
        const float* wme = wbase + (HH == 8 ? l8 : 0) * WBS;
        for (int j = g; j < d; j += 4) {
            int t = ts[j];
            int tt = t < 0 ? 0 : t;
            float w = wme[j];
            float4 p = *reinterpret_cast<const float4*>(hb + tt*CC);
            float4 q = *reinterpret_cast<const float4*>(hb + tt*CC + 4);
            acc[0] = fmaf(w, p.x, acc[0]); acc[1] = fmaf(w, p.y, acc[1]);
            acc[2] = fmaf(w, p.z, acc[2]); acc[3] = fmaf(w, p.w, acc[3]);
            acc[4] = fmaf(w, q.x, acc[4]); acc[5] = fmaf(w, q.y, acc[5]);
            acc[6] = fmaf(w, q.z, acc[6]); acc[7] = fmaf(w, q.w, acc[7]);
        }
    }
    // reduce across the 4 gather groups (l8 preserved by xor 8/16)
    #pragma unroll
    for (int off = 8; off <= 16; off <<= 1)
        #pragma unroll
        for (int i = 0; i < 8; i++)
            acc[i] += __shfl_xor_sync(0xffffffffu, acc[i], off);
    // normalization for my features' head
    float inv;
    if (d == 0) {
        inv = 1.0f / NN;
    } else if (OW == 8) {
        inv = 1.0f / __shfl_sync(0xffffffffu, sw, 4*l8);   // sw uniform in head subgroup
    } else {
        inv = 1.0f / sw;                                    // uniform across warp
    }
    if (g == 0) {
        float4 bz0 = *reinterpret_cast<const float4*>(bias + l8*8);
        float4 bz1 = *reinterpret_cast<const float4*>(bias + l8*8 + 4);
        float z[8];
        z[0]=acc[0]*inv+bz0.x; z[1]=acc[1]*inv+bz0.y; z[2]=acc[2]*inv+bz0.z; z[3]=acc[3]*inv+bz0.w;
        z[4]=acc[4]*inv+bz1.x; z[5]=acc[5]*inv+bz1.y; z[6]=acc[6]*inv+bz1.z; z[7]=acc[7]*inv+bz1.w;
        if (DOELU) {
            #pragma unroll
            for (int i = 0; i < 8; i++) z[i] = z[i] > 0.f ? z[i] : expm1f(z[i]);
        }
        *reinterpret_cast<float4*>(&o[gw*CC + l8*8])     = make_float4(z[0], z[1], z[2], z[3]);
        *reinterpret_cast<float4*>(&o[gw*CC + l8*8 + 4]) = make_float4(z[4], z[5], z[6], z[7]);
    }
}

__global__ void k_agg1(const float* __restrict__ bh) { agg_body<8, 8,  true >(g_h1, g_s1a, g_s2a, bh, g_x1);  }
__global__ void k_agg2(const float* __restrict__ bo) { agg_body<1, 64, false>(g_h2, g_s1b, g_s2b, bo, g_pre); }

// ---------------- log_softmax over node axis + deg re-zero ----------------
// 64 blocks: block = (batch b, 2 features) via float2; 256 threads x 8 rows.
__global__ void k_lsm(float* __restrict__ out) {
    int gt = blockIdx.x * blockDim.x + threadIdx.x;
    if (gt < NN) g_deg[gt] = 0;          // restore invariant for next call

    int b  = blockIdx.x >> 5;
    int f0 = (blockIdx.x & 31) * 2;
    int t  = threadIdx.x;
    float2 v[8];
    float2 mx = make_float2(-INFINITY, -INFINITY);
    #pragma unroll
    for (int i = 0; i < 8; i++) {
        v[i] = *reinterpret_cast<const float2*>(&g_pre[(b*NN + i*256 + t) * CC + f0]);
        mx.x = fmaxf(mx.x, v[i].x); mx.y = fmaxf(mx.y, v[i].y);
    }
    __shared__ float2 red[256];
    red[t] = mx; __syncthreads();
    for (int s = 128; s; s >>= 1) {
        if (t < s) {
            float2 a = red[t], c = red[t + s];
            red[t] = make_float2(fmaxf(a.x,c.x), fmaxf(a.y,c.y));
        }
        __syncthreads();
    }
    mx = red[0];
    __syncthreads();
    float2 sm = make_float2(0.f, 0.f);
    #pragma unroll
    for (int i = 0; i < 8; i++) {
        sm.x += __expf(v[i].x - mx.x); sm.y += __expf(v[i].y - mx.y);
    }
    red[t] = sm; __syncthreads();
    for (int s = 128; s; s >>= 1) {
        if (t < s) {
            float2 a = red[t], c = red[t + s];
            red[t] = make_float2(a.x + c.x, a.y + c.y);
        }
        __syncthreads();
    }
    sm = red[0];
    float2 l = make_float2(mx.x + logf(sm.x), mx.y + logf(sm.y));
    #pragma unroll
    for (int i = 0; i < 8; i++) {
        *reinterpret_cast<float2*>(&out[(b*NN + i*256 + t) * CC + f0]) =
            make_float2(v[i].x - l.x, v[i].y - l.y);
    }
}

// ---------------- launch: 5 kernels ----------------
extern "C" void kernel_launch(void* const* d_in, const int* in_sizes, int n_in,
                              void* d_out, int out_size) {
    const float* x     = (const float*)d_in[0];
    const int*   edges = (const int*)  d_in[1];
    const float* Wh    = (const float*)d_in[2];
    const float* ah    = (const float*)d_in[3];
    const float* bh    = (const float*)d_in[4];
    const float* Wo    = (const float*)d_in[5];
    const float* ao    = (const float*)d_in[6];
    const float* bo    = (const float*)d_in[7];
    float* out = (float*)d_out;
    int E = in_sizes[1] / 2;
    if (E > EMAX) E = EMAX;   // defensive clamp; dataset uses E = 32768

    k_gemm1<<<MM/32, 256>>>(x, Wh, ah, edges, E);   // + adjacency build prologue
    k_agg1 <<<MM/8,  256>>>(bh);
    k_gemm2<<<MM/32, 256>>>(Wo, ao);
    k_agg2 <<<MM/8,  256>>>(bo);
    k_lsm  <<<BB*32, 256>>>(out);                   // + deg re-zero epilogue
}